// round 6
// baseline (speedup 1.0000x reference)
#include <cuda_runtime.h>
#include <math.h>

#define N   384
#define C   128
#define H   4
#define DH  32
#define NN  (N*N)
#define KS  36          // Ksh row stride (floats, mult of 4 -> 16B-aligned rows)
#define VS2 33          // Vsh2 row stride in float2 units

typedef unsigned long long ull;

// Scratch (allocation-free rule: __device__ globals)
__device__ float g_x[NN*C];
__device__ float g_q[NN*C];
__device__ float g_k[NN*C];
__device__ float g_v[NN*C];
__device__ float g_g[NN*C];
__device__ float g_o[NN*C];
__device__ float g_bias[H*NN];

// --------------------------- f32x2 helpers ---------------------------------
__device__ __forceinline__ void ffma2(ull& d, ull a, ull b, ull c) {
    asm("fma.rn.f32x2 %0, %1, %2, %3;" : "=l"(d) : "l"(a), "l"(b), "l"(c));
}
__device__ __forceinline__ ull pack_dup(float a) {
    ull r; asm("mov.b64 %0, {%1, %1};" : "=l"(r) : "f"(a)); return r;
}
__device__ __forceinline__ float hsum2(ull a) {
    float lo, hi; asm("mov.b64 {%0, %1}, %2;" : "=f"(lo), "=f"(hi) : "l"(a));
    return lo + hi;
}

// ---------------------------------------------------------------------------
// LayerNorm over C + per-head pair bias. One warp per 2 rows, float4 lanes.
// ---------------------------------------------------------------------------
__global__ void ln_bias_kernel(const float* __restrict__ pair,
                               const float* __restrict__ ln_w,
                               const float* __restrict__ ln_b,
                               const float* __restrict__ w_bias) {
    int warp = threadIdx.x >> 5, lane = threadIdx.x & 31;
    int row0 = (blockIdx.x * 8 + warp) * 2;
    float4 lw = ((const float4*)ln_w)[lane];
    float4 lb = ((const float4*)ln_b)[lane];
    float4 wb0 = ((const float4*)w_bias)[lane*4 + 0];
    float4 wb1 = ((const float4*)w_bias)[lane*4 + 1];
    float4 wb2 = ((const float4*)w_bias)[lane*4 + 2];
    float4 wb3 = ((const float4*)w_bias)[lane*4 + 3];

    #pragma unroll
    for (int rr = 0; rr < 2; rr++) {
        int row = row0 + rr;
        float4 x = ((const float4*)(pair + (size_t)row * C))[lane];
        float s = x.x + x.y + x.z + x.w;
        #pragma unroll
        for (int o = 16; o; o >>= 1) s += __shfl_xor_sync(0xffffffffu, s, o);
        float mu = s * (1.0f / C);
        float dx = x.x-mu, dy = x.y-mu, dz = x.z-mu, dw = x.w-mu;
        float s2 = dx*dx + dy*dy + dz*dz + dw*dw;
        #pragma unroll
        for (int o = 16; o; o >>= 1) s2 += __shfl_xor_sync(0xffffffffu, s2, o);
        float rstd = rsqrtf(s2 * (1.0f / C) + 1e-5f);
        float4 y;
        y.x = dx*rstd*lw.x + lb.x;
        y.y = dy*rstd*lw.y + lb.y;
        y.z = dz*rstd*lw.z + lb.z;
        y.w = dw*rstd*lw.w + lb.w;
        ((float4*)(g_x + (size_t)row * C))[lane] = y;

        float4 bs;
        bs.x = y.x*wb0.x + y.y*wb1.x + y.z*wb2.x + y.w*wb3.x;
        bs.y = y.x*wb0.y + y.y*wb1.y + y.z*wb2.y + y.w*wb3.y;
        bs.z = y.x*wb0.z + y.y*wb1.z + y.z*wb2.z + y.w*wb3.z;
        bs.w = y.x*wb0.w + y.y*wb1.w + y.z*wb2.w + y.w*wb3.w;
        #pragma unroll
        for (int o = 16; o; o >>= 1) {
            bs.x += __shfl_xor_sync(0xffffffffu, bs.x, o);
            bs.y += __shfl_xor_sync(0xffffffffu, bs.y, o);
            bs.z += __shfl_xor_sync(0xffffffffu, bs.z, o);
            bs.w += __shfl_xor_sync(0xffffffffu, bs.w, o);
        }
        if (lane == 0) {
            g_bias[0*NN + row] = bs.x;
            g_bias[1*NN + row] = bs.y;
            g_bias[2*NN + row] = bs.z;
            g_bias[3*NN + row] = bs.w;
        }
    }
}

// ---------------------------------------------------------------------------
// Fused multi-weight SGEMM. Block tile 128 rows x 64 cols, 8x4 register tile,
// inner product in packed f32x2 (2 FFMA2 per (r,kk) on adjacent W columns).
// ---------------------------------------------------------------------------
__global__ __launch_bounds__(256) void gemm_fused_kernel(
    const float* __restrict__ A, const float* __restrict__ A2,
    const float* __restrict__ W0, const float* __restrict__ W1,
    const float* __restrict__ W2, const float* __restrict__ W3,
    float* __restrict__ O0, float* __restrict__ O1,
    float* __restrict__ O2, float* __restrict__ O3,
    int nit, int sigmask)
{
    extern __shared__ float sm[];
    float* As = sm;             // [128][128]
    float* Ws = sm + 128*128;   // [128][64]
    const float* Wlist[4] = {W0, W1, W2, W3};
    float*       Olist[4] = {O0, O1, O2, O3};

    int rowBase = blockIdx.x * 128;
    int tid = threadIdx.x;
    const float* Ap = A + (size_t)rowBase * C;
    if (A2) {
        const float* A2p = A2 + (size_t)rowBase * C;
        #pragma unroll
        for (int i = tid*4; i < 128*128; i += 1024) {
            float4 a = *(const float4*)&Ap[i];
            float4 b = *(const float4*)&A2p[i];
            a.x *= b.x; a.y *= b.y; a.z *= b.z; a.w *= b.w;
            *(float4*)&As[i] = a;
        }
    } else {
        #pragma unroll
        for (int i = tid*4; i < 128*128; i += 1024)
            *(float4*)&As[i] = *(const float4*)&Ap[i];
    }

    int tx = tid & 15, ty = tid >> 4;

    for (int it = 0; it < nit; it++) {
        int w = it >> 1;
        int colBase = (it & 1) * 64;
        const float* W = Wlist[w];
        __syncthreads();
        #pragma unroll
        for (int i = tid*4; i < 128*64; i += 1024) {
            int kr = i >> 6, kc = i & 63;
            *(float4*)&Ws[i] = *(const float4*)&W[kr * C + colBase + kc];
        }
        __syncthreads();

        ull acc2[8][2];
        #pragma unroll
        for (int r = 0; r < 8; r++) { acc2[r][0] = 0ull; acc2[r][1] = 0ull; }

        for (int k0 = 0; k0 < 128; k0 += 4) {
            float av[8][4]; ulonglong2 bv[4];
            #pragma unroll
            for (int kk = 0; kk < 4; kk++)
                bv[kk] = *(const ulonglong2*)&Ws[(k0 + kk)*64 + tx*4];
            #pragma unroll
            for (int r = 0; r < 8; r++)
                *(float4*)av[r] = *(const float4*)&As[(ty*8 + r)*128 + k0];
            #pragma unroll
            for (int r = 0; r < 8; r++)
                #pragma unroll
                for (int kk = 0; kk < 4; kk++) {
                    ull a2 = pack_dup(av[r][kk]);
                    ffma2(acc2[r][0], a2, bv[kk].x, acc2[r][0]);
                    ffma2(acc2[r][1], a2, bv[kk].y, acc2[r][1]);
                }
        }

        int sig = (sigmask >> w) & 1;
        float* O = Olist[w];
        #pragma unroll
        for (int r = 0; r < 8; r++) {
            float lo0, hi0, lo1, hi1;
            asm("mov.b64 {%0, %1}, %2;" : "=f"(lo0), "=f"(hi0) : "l"(acc2[r][0]));
            asm("mov.b64 {%0, %1}, %2;" : "=f"(lo1), "=f"(hi1) : "l"(acc2[r][1]));
            float4 v = make_float4(lo0, hi0, lo1, hi1);
            if (sig) {
                v.x = 1.f/(1.f + __expf(-v.x));
                v.y = 1.f/(1.f + __expf(-v.y));
                v.z = 1.f/(1.f + __expf(-v.z));
                v.w = 1.f/(1.f + __expf(-v.w));
            }
            *(float4*)&O[((size_t)rowBase + ty*8 + r)*C + colBase + tx*4] = v;
        }
    }
}

// ---------------------------------------------------------------------------
// Attention: one block (256 thr, 8 warps) per (b,h). 8 q-rows per warp-group
// amortize every K/V smem read. QK: 4 passes x 3 k-columns, d paired via
// f32x2 with LDS.128 K reads. Softmax stores UNNORMALIZED exp; 1/s folded
// into the O store. PV: paired over k with pre-packed V, shared by 8 rows.
// ---------------------------------------------------------------------------
__global__ __launch_bounds__(256) void attn_kernel(const int* __restrict__ mask) {
    extern __shared__ float sm[];
    float* Ksh   = sm;                        // [384][36]
    float* Vsh2f = Ksh + N*KS;                // 192 x [VS2 float2] (packed k-pairs)
    float* Psh   = Vsh2f + 192*VS2*2;         // 8 warps x [8][384]
    float* Qsh   = Psh + 8*8*N;               // 8 warps x [8][32]
    int b = blockIdx.x, h = blockIdx.y;
    int tid = threadIdx.x, warp = tid >> 5, lane = tid & 31;

    const float* Kg = g_k + (size_t)b*N*C + h*DH;
    const float* Vg = g_v + (size_t)b*N*C + h*DH;
    for (int i = tid; i < N*DH; i += 256) {
        int r = i >> 5, d = i & 31;
        Ksh[r*KS + d] = Kg[(size_t)r*C + d];
        // pack V k-pairs: Vsh2[k>>1][d] = {V[k_even][d], V[k_odd][d]}
        Vsh2f[(r >> 1)*(VS2*2) + d*2 + (r & 1)] = Vg[(size_t)r*C + d];
    }
    __syncthreads();

    bool mk[12];
    const int* mrow = mask + b*N;
    #pragma unroll
    for (int i = 0; i < 12; i++) mk[i] = mrow[lane + 32*i] > 0;

    float* Pw = Psh + warp * (8*N);
    float* Qw = Qsh + warp * 256;
    const ull* V2 = (const ull*)Vsh2f;
    const float* biasH = g_bias + (size_t)h*NN;
    const float scale = 0.17677669529663687f;   // 1/sqrt(32)

    for (int grp = warp; grp < 48; grp += 8) {
        int q0 = grp * 8;
        #pragma unroll
        for (int r = 0; r < 8; r++)
            Qw[r*32 + lane] = g_q[((size_t)b*N + q0 + r)*C + h*DH + lane];
        __syncwarp();

        // ---- QK: 4 passes of 3 k-columns; 8 rows share each K read ----
        #pragma unroll
        for (int pass = 0; pass < 4; pass++) {
            ull acc2[8][3];
            #pragma unroll
            for (int r = 0; r < 8; r++)
                #pragma unroll
                for (int ii = 0; ii < 3; ii++) acc2[r][ii] = 0ull;

            #pragma unroll 2
            for (int dp = 0; dp < 8; dp++) {      // 4 d per iter
                ulonglong2 q2[8];
                #pragma unroll
                for (int r = 0; r < 8; r++)
                    q2[r] = *(const ulonglong2*)&Qw[r*32 + 4*dp];
                #pragma unroll
                for (int ii = 0; ii < 3; ii++) {
                    int i = pass*3 + ii;
                    ulonglong2 k2 = *(const ulonglong2*)&Ksh[(lane + 32*i)*KS + 4*dp];
                    #pragma unroll
                    for (int r = 0; r < 8; r++) {
                        ffma2(acc2[r][ii], q2[r].x, k2.x, acc2[r][ii]);
                        ffma2(acc2[r][ii], q2[r].y, k2.y, acc2[r][ii]);
                    }
                }
            }
            #pragma unroll
            for (int r = 0; r < 8; r++)
                #pragma unroll
                for (int ii = 0; ii < 3; ii++)
                    Pw[r*N + lane + 32*(pass*3 + ii)] = hsum2(acc2[r][ii]);
        }

        // ---- softmax: raw logits -> unnormalized exp (1/s kept per row) ----
        float inv8[8];
        #pragma unroll
        for (int r = 0; r < 8; r++) {
            const float* brow = biasH + (size_t)(q0 + r)*N;
            float vals[12];
            float m = -3.0e38f;
            #pragma unroll
            for (int i = 0; i < 12; i++) {
                float v = mk[i] ? (Pw[r*N + lane + 32*i]*scale + brow[lane + 32*i])
                                : -1e9f;
                vals[i] = v;
                m = fmaxf(m, v);
            }
            #pragma unroll
            for (int o = 16; o; o >>= 1) m = fmaxf(m, __shfl_xor_sync(0xffffffffu, m, o));
            float s = 0.f;
            #pragma unroll
            for (int i = 0; i < 12; i++) { float e = __expf(vals[i] - m); vals[i] = e; s += e; }
            #pragma unroll
            for (int o = 16; o; o >>= 1) s += __shfl_xor_sync(0xffffffffu, s, o);
            inv8[r] = 1.f / s;
            #pragma unroll
            for (int i = 0; i < 12; i++) Pw[r*N + lane + 32*i] = vals[i];
        }
        __syncwarp();

        // ---- PV: paired over k; each V pair shared by 8 rows ----
        ull o2[8];
        #pragma unroll
        for (int r = 0; r < 8; r++) o2[r] = 0ull;
        #pragma unroll 2
        for (int k0 = 0; k0 < N; k0 += 4) {
            int k2a = k0 >> 1;
            ull va = V2[(size_t)k2a*VS2 + lane];
            ull vb = V2[(size_t)(k2a+1)*VS2 + lane];
            #pragma unroll
            for (int r = 0; r < 8; r++) {
                ulonglong2 pp = *(const ulonglong2*)&Pw[r*N + k0];
                ffma2(o2[r], pp.x, va, o2[r]);
                ffma2(o2[r], pp.y, vb, o2[r]);
            }
        }
        float* Og = g_o + ((size_t)b*N + q0)*C + h*DH + lane;
        #pragma unroll
        for (int r = 0; r < 8; r++) Og[r*C] = hsum2(o2[r]) * inv8[r];
        __syncwarp();
    }
}

// ---------------------------------------------------------------------------
extern "C" void kernel_launch(void* const* d_in, const int* in_sizes, int n_in,
                              void* d_out, int out_size) {
    const float* pair   = (const float*)d_in[0];
    const int*   mask   = (const int*)  d_in[1];
    const float* ln_w   = (const float*)d_in[2];
    const float* ln_b   = (const float*)d_in[3];
    const float* w_bias = (const float*)d_in[4];
    const float* wq     = (const float*)d_in[5];
    const float* wk     = (const float*)d_in[6];
    const float* wv     = (const float*)d_in[7];
    const float* wg     = (const float*)d_in[8];
    const float* wo     = (const float*)d_in[9];

    float *gx, *gq, *gk, *gv, *gg, *go;
    cudaGetSymbolAddress((void**)&gx, g_x);
    cudaGetSymbolAddress((void**)&gq, g_q);
    cudaGetSymbolAddress((void**)&gk, g_k);
    cudaGetSymbolAddress((void**)&gv, g_v);
    cudaGetSymbolAddress((void**)&gg, g_g);
    cudaGetSymbolAddress((void**)&go, g_o);

    size_t gemm_smem = (size_t)(128*128 + 128*64) * sizeof(float);   // 96 KB
    size_t attn_smem = (size_t)(N*KS + 192*VS2*2 + 8*8*N + 8*256) * sizeof(float); // ~212.5 KB
    cudaFuncSetAttribute(gemm_fused_kernel, cudaFuncAttributeMaxDynamicSharedMemorySize,
                         (int)gemm_smem);
    cudaFuncSetAttribute(attn_kernel, cudaFuncAttributeMaxDynamicSharedMemorySize,
                         (int)attn_smem);

    ln_bias_kernel<<<NN/16, 256>>>(pair, ln_w, ln_b, w_bias);

    // Fused Q/K/V/Gate projections (gate gets sigmoid: w index 3 -> bit 3)
    gemm_fused_kernel<<<NN/128, 256, gemm_smem>>>(
        gx, nullptr, wq, wk, wv, wg, gq, gk, gv, gg, 8, 8);

    attn_kernel<<<dim3(N, H), 256, attn_smem>>>(mask);

    // Output projection: (o * gate) @ wo
    gemm_fused_kernel<<<NN/128, 256, gemm_smem>>>(
        go, gg, wo, nullptr, nullptr, nullptr, (float*)d_out, nullptr, nullptr, nullptr, 2, 0);
}

// round 8
// speedup vs baseline: 1.9049x; 1.9049x over previous
#include <cuda_runtime.h>
#include <cuda_bf16.h>
#include <math.h>
#include <stdint.h>

#define N   384
#define C   128
#define H   4
#define DH  32
#define NN  (N*N)
typedef unsigned long long ull;
typedef uint32_t u32;

// Scratch (allocation-free rule: __device__ globals)
__device__ __align__(16) float g_x[NN*C];
__device__ __align__(16) float g_g[NN*C];
__device__ __align__(16) float g_o[NN*C];
__device__ __align__(16) float g_bias[H*NN];
__device__ __align__(16) __nv_bfloat16 g_qh[NN*C], g_ql[NN*C];
__device__ __align__(16) __nv_bfloat16 g_kh[NN*C], g_kl[NN*C];
__device__ __align__(16) __nv_bfloat16 g_vh[NN*C], g_vl[NN*C];

// --------------------------- helpers ---------------------------------------
__device__ __forceinline__ void ffma2(ull& d, ull a, ull b, ull c) {
    asm("fma.rn.f32x2 %0, %1, %2, %3;" : "=l"(d) : "l"(a), "l"(b), "l"(c));
}
__device__ __forceinline__ ull pack_dup(float a) {
    ull r; asm("mov.b64 %0, {%1, %1};" : "=l"(r) : "f"(a)); return r;
}
__device__ __forceinline__ u32 pack_bf2(float a, float b) {   // a->low, b->high
    __nv_bfloat162 t = __floats2bfloat162_rn(a, b); return *(u32*)&t;
}
__device__ __forceinline__ float lo_f(u32 u) { return __uint_as_float(u << 16); }
__device__ __forceinline__ float hi_f(u32 u) { return __uint_as_float(u & 0xFFFF0000u); }

// bf16 warp MMA: D[16x8] += A[16x16] * B[16x8] (A row-major, B col-major)
__device__ __forceinline__ void mma16816(float* d, const u32* a, u32 b0, u32 b1) {
    asm volatile("mma.sync.aligned.m16n8k16.row.col.f32.bf16.bf16.f32 "
        "{%0,%1,%2,%3}, {%4,%5,%6,%7}, {%8,%9}, {%0,%1,%2,%3};"
        : "+f"(d[0]), "+f"(d[1]), "+f"(d[2]), "+f"(d[3])
        : "r"(a[0]), "r"(a[1]), "r"(a[2]), "r"(a[3]), "r"(b0), "r"(b1));
}

// ---------------------------------------------------------------------------
// LayerNorm + per-head pair bias (one warp per 2 rows)
// ---------------------------------------------------------------------------
__global__ void ln_bias_kernel(const float* __restrict__ pair,
                               const float* __restrict__ ln_w,
                               const float* __restrict__ ln_b,
                               const float* __restrict__ w_bias) {
    int warp = threadIdx.x >> 5, lane = threadIdx.x & 31;
    int row0 = (blockIdx.x * 8 + warp) * 2;
    float4 lw = ((const float4*)ln_w)[lane];
    float4 lb = ((const float4*)ln_b)[lane];
    float4 wb0 = ((const float4*)w_bias)[lane*4 + 0];
    float4 wb1 = ((const float4*)w_bias)[lane*4 + 1];
    float4 wb2 = ((const float4*)w_bias)[lane*4 + 2];
    float4 wb3 = ((const float4*)w_bias)[lane*4 + 3];
    #pragma unroll
    for (int rr = 0; rr < 2; rr++) {
        int row = row0 + rr;
        float4 x = ((const float4*)(pair + (size_t)row * C))[lane];
        float s = x.x + x.y + x.z + x.w;
        #pragma unroll
        for (int o = 16; o; o >>= 1) s += __shfl_xor_sync(0xffffffffu, s, o);
        float mu = s * (1.0f / C);
        float dx = x.x-mu, dy = x.y-mu, dz = x.z-mu, dw = x.w-mu;
        float s2 = dx*dx + dy*dy + dz*dz + dw*dw;
        #pragma unroll
        for (int o = 16; o; o >>= 1) s2 += __shfl_xor_sync(0xffffffffu, s2, o);
        float rstd = rsqrtf(s2 * (1.0f / C) + 1e-5f);
        float4 y;
        y.x = dx*rstd*lw.x + lb.x;  y.y = dy*rstd*lw.y + lb.y;
        y.z = dz*rstd*lw.z + lb.z;  y.w = dw*rstd*lw.w + lb.w;
        ((float4*)(g_x + (size_t)row * C))[lane] = y;
        float4 bs;
        bs.x = y.x*wb0.x + y.y*wb1.x + y.z*wb2.x + y.w*wb3.x;
        bs.y = y.x*wb0.y + y.y*wb1.y + y.z*wb2.y + y.w*wb3.y;
        bs.z = y.x*wb0.z + y.y*wb1.z + y.z*wb2.z + y.w*wb3.z;
        bs.w = y.x*wb0.w + y.y*wb1.w + y.z*wb2.w + y.w*wb3.w;
        #pragma unroll
        for (int o = 16; o; o >>= 1) {
            bs.x += __shfl_xor_sync(0xffffffffu, bs.x, o);
            bs.y += __shfl_xor_sync(0xffffffffu, bs.y, o);
            bs.z += __shfl_xor_sync(0xffffffffu, bs.z, o);
            bs.w += __shfl_xor_sync(0xffffffffu, bs.w, o);
        }
        if (lane == 0) {
            g_bias[0*NN + row] = bs.x;  g_bias[1*NN + row] = bs.y;
            g_bias[2*NN + row] = bs.z;  g_bias[3*NN + row] = bs.w;
        }
    }
}

// ---------------------------------------------------------------------------
// QKVG projections (fp32 FFMA2 inner loop). Q/K/V written as SPLIT bf16
// hi/lo arrays; gate written fp32 with sigmoid.
// ---------------------------------------------------------------------------
__global__ __launch_bounds__(256) void proj_qkvg_kernel(
    const float* __restrict__ W0, const float* __restrict__ W1,
    const float* __restrict__ W2, const float* __restrict__ W3)
{
    extern __shared__ float sm[];
    float* As = sm;             // [128][128]
    float* Ws = sm + 128*128;   // [128][64]
    const float* Wlist[4] = {W0, W1, W2, W3};
    int rowBase = blockIdx.x * 128;
    int tid = threadIdx.x;
    const float* Ap = g_x + (size_t)rowBase * C;
    #pragma unroll
    for (int i = tid*4; i < 128*128; i += 1024)
        *(float4*)&As[i] = *(const float4*)&Ap[i];

    int tx = tid & 15, ty = tid >> 4;
    for (int it = 0; it < 8; it++) {
        int w = it >> 1;
        int colBase = (it & 1) * 64;
        const float* W = Wlist[w];
        __syncthreads();
        #pragma unroll
        for (int i = tid*4; i < 128*64; i += 1024) {
            int kr = i >> 6, kc = i & 63;
            *(float4*)&Ws[i] = *(const float4*)&W[kr * C + colBase + kc];
        }
        __syncthreads();

        ull acc2[8][2];
        #pragma unroll
        for (int r = 0; r < 8; r++) { acc2[r][0] = 0ull; acc2[r][1] = 0ull; }
        for (int k0 = 0; k0 < 128; k0 += 4) {
            float av[8][4]; ulonglong2 bv[4];
            #pragma unroll
            for (int kk = 0; kk < 4; kk++)
                bv[kk] = *(const ulonglong2*)&Ws[(k0 + kk)*64 + tx*4];
            #pragma unroll
            for (int r = 0; r < 8; r++)
                *(float4*)av[r] = *(const float4*)&As[(ty*8 + r)*128 + k0];
            #pragma unroll
            for (int r = 0; r < 8; r++)
                #pragma unroll
                for (int kk = 0; kk < 4; kk++) {
                    ull a2 = pack_dup(av[r][kk]);
                    ffma2(acc2[r][0], a2, bv[kk].x, acc2[r][0]);
                    ffma2(acc2[r][1], a2, bv[kk].y, acc2[r][1]);
                }
        }

        __nv_bfloat16* Oh = (w == 0) ? g_qh : (w == 1) ? g_kh : g_vh;
        __nv_bfloat16* Ol = (w == 0) ? g_ql : (w == 1) ? g_kl : g_vl;
        #pragma unroll
        for (int r = 0; r < 8; r++) {
            float vx, vy, vz, vw;
            asm("mov.b64 {%0, %1}, %2;" : "=f"(vx), "=f"(vy) : "l"(acc2[r][0]));
            asm("mov.b64 {%0, %1}, %2;" : "=f"(vz), "=f"(vw) : "l"(acc2[r][1]));
            size_t row = (size_t)rowBase + ty*8 + r;
            if (w < 3) {
                u32 h0 = pack_bf2(vx, vy), h1 = pack_bf2(vz, vw);
                u32 l0 = pack_bf2(vx - lo_f(h0), vy - hi_f(h0));
                u32 l1 = pack_bf2(vz - lo_f(h1), vw - hi_f(h1));
                u32* oh = (u32*)Oh + row*64 + (colBase >> 1) + tx*2;
                u32* ol = (u32*)Ol + row*64 + (colBase >> 1) + tx*2;
                oh[0] = h0; oh[1] = h1; ol[0] = l0; ol[1] = l1;
            } else {
                float4 v;
                v.x = 1.f/(1.f + __expf(-vx)); v.y = 1.f/(1.f + __expf(-vy));
                v.z = 1.f/(1.f + __expf(-vz)); v.w = 1.f/(1.f + __expf(-vw));
                *(float4*)&g_g[row*C + colBase + tx*4] = v;
            }
        }
    }
}

// ---------------------------------------------------------------------------
// Output projection: (o * gate) @ wo  (fp32 FFMA2)
// ---------------------------------------------------------------------------
__global__ __launch_bounds__(256) void gemm_out_kernel(const float* __restrict__ W,
                                                       float* __restrict__ Out) {
    extern __shared__ float sm[];
    float* As = sm;
    float* Ws = sm + 128*128;
    int rowBase = blockIdx.x * 128;
    int tid = threadIdx.x;
    const float* Ap = g_o + (size_t)rowBase * C;
    const float* A2p = g_g + (size_t)rowBase * C;
    #pragma unroll
    for (int i = tid*4; i < 128*128; i += 1024) {
        float4 a = *(const float4*)&Ap[i];
        float4 b = *(const float4*)&A2p[i];
        a.x *= b.x; a.y *= b.y; a.z *= b.z; a.w *= b.w;
        *(float4*)&As[i] = a;
    }
    int tx = tid & 15, ty = tid >> 4;
    for (int it = 0; it < 2; it++) {
        int colBase = it * 64;
        __syncthreads();
        #pragma unroll
        for (int i = tid*4; i < 128*64; i += 1024) {
            int kr = i >> 6, kc = i & 63;
            *(float4*)&Ws[i] = *(const float4*)&W[kr * C + colBase + kc];
        }
        __syncthreads();
        ull acc2[8][2];
        #pragma unroll
        for (int r = 0; r < 8; r++) { acc2[r][0] = 0ull; acc2[r][1] = 0ull; }
        for (int k0 = 0; k0 < 128; k0 += 4) {
            float av[8][4]; ulonglong2 bv[4];
            #pragma unroll
            for (int kk = 0; kk < 4; kk++)
                bv[kk] = *(const ulonglong2*)&Ws[(k0 + kk)*64 + tx*4];
            #pragma unroll
            for (int r = 0; r < 8; r++)
                *(float4*)av[r] = *(const float4*)&As[(ty*8 + r)*128 + k0];
            #pragma unroll
            for (int r = 0; r < 8; r++)
                #pragma unroll
                for (int kk = 0; kk < 4; kk++) {
                    ull a2 = pack_dup(av[r][kk]);
                    ffma2(acc2[r][0], a2, bv[kk].x, acc2[r][0]);
                    ffma2(acc2[r][1], a2, bv[kk].y, acc2[r][1]);
                }
        }
        #pragma unroll
        for (int r = 0; r < 8; r++) {
            float vx, vy, vz, vw;
            asm("mov.b64 {%0, %1}, %2;" : "=f"(vx), "=f"(vy) : "l"(acc2[r][0]));
            asm("mov.b64 {%0, %1}, %2;" : "=f"(vz), "=f"(vw) : "l"(acc2[r][1]));
            *(float4*)&Out[((size_t)rowBase + ty*8 + r)*C + colBase + tx*4] =
                make_float4(vx, vy, vz, vw);
        }
    }
}

// ---------------------------------------------------------------------------
// Attention via mma.sync (HMMA 16816 bf16, hi/lo split = 3 MMAs/product).
// Block = (b,h), 384 threads, warp owns 32 q-rows (2 m-tiles sequentially).
// Streaming fixed-max softmax: exp(scale*s + bias + madd), madd = mask-4.
// QK D-fragment pair reused directly as PV A-fragment (register-layout match).
// SMEM: madd[384] | Kh/Kl [384][40 bf16] | Vth/Vtl [32][392 bf16].
// ---------------------------------------------------------------------------
#define SM_MADD 0
#define SM_KH   1536
#define SM_KL   (SM_KH + 30720)
#define SM_VTH  (SM_KL + 30720)
#define SM_VTL  (SM_VTH + 25088)
#define AT_SMEM (SM_VTL + 25088)

__global__ __launch_bounds__(384) void attn_mma_kernel(const int* __restrict__ mask) {
    extern __shared__ char smem[];
    float* madd = (float*)(smem + SM_MADD);
    u32* Khs = (u32*)(smem + SM_KH);          // row stride 20 u32
    u32* Kls = (u32*)(smem + SM_KL);
    uint16_t* Vth = (uint16_t*)(smem + SM_VTH);   // [32 d][392 keys]
    uint16_t* Vtl = (uint16_t*)(smem + SM_VTL);

    int b = blockIdx.x, h = blockIdx.y;
    int tid = threadIdx.x, warp = tid >> 5, lane = tid & 31;
    int g = lane >> 2, t = lane & 3;
    const float scale = 0.17677669529663687f;   // 1/sqrt(32)

    const u32* KH = (const u32*)g_kh;  const u32* KL = (const u32*)g_kl;
    const u32* VH = (const u32*)g_vh;  const u32* VL = (const u32*)g_vl;
    const u32* QH = (const u32*)g_qh;  const u32* QL = (const u32*)g_ql;

    for (int i = tid; i < N; i += 384)
        madd[i] = (mask[b*N + i] > 0 ? 0.f : -1e9f) - 4.0f;
    for (int i = tid; i < N*16; i += 384) {
        int key = i >> 4, dp = i & 15;
        size_t gi = (size_t)(b*N + key)*64 + h*16 + dp;
        Khs[key*20 + dp] = KH[gi];
        Kls[key*20 + dp] = KL[gi];
        u32 vh = VH[gi], vl = VL[gi];
        Vth[(2*dp)*392 + key]   = (uint16_t)(vh & 0xFFFFu);
        Vth[(2*dp+1)*392 + key] = (uint16_t)(vh >> 16);
        Vtl[(2*dp)*392 + key]   = (uint16_t)(vl & 0xFFFFu);
        Vtl[(2*dp+1)*392 + key] = (uint16_t)(vl >> 16);
    }
    __syncthreads();

    const u32* Vth32 = (const u32*)Vth;   // row stride 196 u32
    const u32* Vtl32 = (const u32*)Vtl;

    for (int mt = 0; mt < 2; mt++) {
        int qb = warp*32 + mt*16;
        // Q fragments straight from gmem
        u32 qh[2][4], ql[2][4];
        #pragma unroll
        for (int ks = 0; ks < 2; ks++) {
            size_t base0 = (size_t)(b*N + qb + g)*64 + h*16 + ks*8 + t;
            size_t base1 = base0 + 8*64;
            qh[ks][0] = QH[base0];     qh[ks][1] = QH[base1];
            qh[ks][2] = QH[base0 + 4]; qh[ks][3] = QH[base1 + 4];
            ql[ks][0] = QL[base0];     ql[ks][1] = QL[base1];
            ql[ks][2] = QL[base0 + 4]; ql[ks][3] = QL[base1 + 4];
        }
        float oacc[4][4];
        #pragma unroll
        for (int dt = 0; dt < 4; dt++)
            #pragma unroll
            for (int j = 0; j < 4; j++) oacc[dt][j] = 0.f;
        float sum0 = 0.f, sum1 = 0.f;
        const float* bias0 = g_bias + (size_t)h*NN + (size_t)(qb + g)*N;
        const float* bias1 = bias0 + 8*N;

        for (int kb = 0; kb < N; kb += 16) {
            float s0[4] = {0.f,0.f,0.f,0.f}, s1[4] = {0.f,0.f,0.f,0.f};
            #pragma unroll
            for (int ks = 0; ks < 2; ks++) {
                int k0 = (kb + g)*20 + ks*8 + t;
                int k1 = k0 + 8*20;
                u32 b0h = Khs[k0], b1h = Khs[k0+4];
                u32 b0l = Kls[k0], b1l = Kls[k0+4];
                mma16816(s0, qh[ks], b0h, b1h);
                mma16816(s0, qh[ks], b0l, b1l);
                mma16816(s0, ql[ks], b0h, b1h);
                u32 c0h = Khs[k1], c1h = Khs[k1+4];
                u32 c0l = Kls[k1], c1l = Kls[k1+4];
                mma16816(s1, qh[ks], c0h, c1h);
                mma16816(s1, qh[ks], c0l, c1l);
                mma16816(s1, ql[ks], c0h, c1h);
            }
            // bias + mask + scale + exp (fixed-max)
            float2 bA0 = *(const float2*)&bias0[kb + 2*t];
            float2 bB0 = *(const float2*)&bias1[kb + 2*t];
            float2 bA1 = *(const float2*)&bias0[kb + 8 + 2*t];
            float2 bB1 = *(const float2*)&bias1[kb + 8 + 2*t];
            float2 mA0 = *(const float2*)&madd[kb + 2*t];
            float2 mA1 = *(const float2*)&madd[kb + 8 + 2*t];
            float e00 = __expf(fmaf(s0[0], scale, bA0.x + mA0.x));
            float e01 = __expf(fmaf(s0[1], scale, bA0.y + mA0.y));
            float e02 = __expf(fmaf(s0[2], scale, bB0.x + mA0.x));
            float e03 = __expf(fmaf(s0[3], scale, bB0.y + mA0.y));
            float e10 = __expf(fmaf(s1[0], scale, bA1.x + mA1.x));
            float e11 = __expf(fmaf(s1[1], scale, bA1.y + mA1.y));
            float e12 = __expf(fmaf(s1[2], scale, bB1.x + mA1.x));
            float e13 = __expf(fmaf(s1[3], scale, bB1.y + mA1.y));
            sum0 += (e00 + e01) + (e10 + e11);
            sum1 += (e02 + e03) + (e12 + e13);
            // P fragments: QK D-layout == PV A-layout
            u32 ah[4], al[4];
            ah[0] = pack_bf2(e00, e01);  ah[1] = pack_bf2(e02, e03);
            ah[2] = pack_bf2(e10, e11);  ah[3] = pack_bf2(e12, e13);
            al[0] = pack_bf2(e00 - lo_f(ah[0]), e01 - hi_f(ah[0]));
            al[1] = pack_bf2(e02 - lo_f(ah[1]), e03 - hi_f(ah[1]));
            al[2] = pack_bf2(e10 - lo_f(ah[2]), e11 - hi_f(ah[2]));
            al[3] = pack_bf2(e12 - lo_f(ah[3]), e13 - hi_f(ah[3]));
            // PV
            int kcol = (kb >> 1) + t;
            #pragma unroll
            for (int dt = 0; dt < 4; dt++) {
                int vr = (dt*8 + g)*196;
                u32 v0h = Vth32[vr + kcol], v1h = Vth32[vr + kcol + 4];
                u32 v0l = Vtl32[vr + kcol], v1l = Vtl32[vr + kcol + 4];
                mma16816(oacc[dt], ah, v0h, v1h);
                mma16816(oacc[dt], ah, v0l, v1l);
                mma16816(oacc[dt], al, v0h, v1h);
            }
        }
        // row sums live on 4 lanes each (lane%4 varies) -> butterfly
        sum0 += __shfl_xor_sync(0xffffffffu, sum0, 1);
        sum0 += __shfl_xor_sync(0xffffffffu, sum0, 2);
        sum1 += __shfl_xor_sync(0xffffffffu, sum1, 1);
        sum1 += __shfl_xor_sync(0xffffffffu, sum1, 2);
        float inv0 = 1.f / sum0, inv1 = 1.f / sum1;
        float* o0 = g_o + (size_t)(b*N + qb + g)*C + h*DH;
        float* o1 = o0 + 8*C;
        #pragma unroll
        for (int dt = 0; dt < 4; dt++) {
            *(float2*)&o0[dt*8 + 2*t] = make_float2(oacc[dt][0]*inv0, oacc[dt][1]*inv0);
            *(float2*)&o1[dt*8 + 2*t] = make_float2(oacc[dt][2]*inv1, oacc[dt][3]*inv1);
        }
    }
}

// ---------------------------------------------------------------------------
extern "C" void kernel_launch(void* const* d_in, const int* in_sizes, int n_in,
                              void* d_out, int out_size) {
    const float* pair   = (const float*)d_in[0];
    const int*   mask   = (const int*)  d_in[1];
    const float* ln_w   = (const float*)d_in[2];
    const float* ln_b   = (const float*)d_in[3];
    const float* w_bias = (const float*)d_in[4];
    const float* wq     = (const float*)d_in[5];
    const float* wk     = (const float*)d_in[6];
    const float* wv     = (const float*)d_in[7];
    const float* wg     = (const float*)d_in[8];
    const float* wo     = (const float*)d_in[9];

    size_t gemm_smem = (size_t)(128*128 + 128*64) * sizeof(float);   // 96 KB
    cudaFuncSetAttribute(proj_qkvg_kernel, cudaFuncAttributeMaxDynamicSharedMemorySize,
                         (int)gemm_smem);
    cudaFuncSetAttribute(gemm_out_kernel, cudaFuncAttributeMaxDynamicSharedMemorySize,
                         (int)gemm_smem);
    cudaFuncSetAttribute(attn_mma_kernel, cudaFuncAttributeMaxDynamicSharedMemorySize,
                         AT_SMEM);

    ln_bias_kernel<<<NN/16, 256>>>(pair, ln_w, ln_b, w_bias);
    proj_qkvg_kernel<<<NN/128, 256, gemm_smem>>>(wq, wk, wv, wg);
    attn_mma_kernel<<<dim3(N, H), 384, AT_SMEM>>>(mask);
    gemm_out_kernel<<<NN/128, 256, gemm_smem>>>(wo, (float*)d_out);
}

// round 9
// speedup vs baseline: 2.1279x; 1.1171x over previous
#include <cuda_runtime.h>
#include <cuda_bf16.h>
#include <math.h>
#include <stdint.h>

#define N   384
#define C   128
#define H   4
#define DH  32
#define NN  (N*N)
#define WPAD 136               // bf16 per smem row (k-stride), conflict-free
typedef unsigned long long ull;
typedef uint32_t u32;

// Scratch (allocation-free rule: __device__ globals)
__device__ __align__(16) float g_g[NN*C];
__device__ __align__(16) float g_o[NN*C];
__device__ __align__(16) float g_bias[H*NN];
__device__ __align__(16) __nv_bfloat16 g_xh[NN*C], g_xl[NN*C];
__device__ __align__(16) __nv_bfloat16 g_qh[NN*C], g_ql[NN*C];
__device__ __align__(16) __nv_bfloat16 g_kh[NN*C], g_kl[NN*C];
__device__ __align__(16) __nv_bfloat16 g_vh[NN*C], g_vl[NN*C];
__device__ __align__(16) __nv_bfloat16 g_wh[5*C*WPAD], g_wl[5*C*WPAD];  // W^T [w][n][k]

// --------------------------- helpers ---------------------------------------
__device__ __forceinline__ u32 pack_bf2(float a, float b) {   // a->low, b->high
    __nv_bfloat162 t = __floats2bfloat162_rn(a, b); return *(u32*)&t;
}
__device__ __forceinline__ float lo_f(u32 u) { return __uint_as_float(u << 16); }
__device__ __forceinline__ float hi_f(u32 u) { return __uint_as_float(u & 0xFFFF0000u); }
__device__ __forceinline__ u32 smem_u32(const void* p) {
    u32 a; asm("{ .reg .u64 t; cvta.to.shared.u64 t, %1; cvt.u32.u64 %0, t; }"
               : "=r"(a) : "l"(p));
    return a;
}
// bf16 warp MMA: D[16x8] += A[16x16] * B[16x8] (A row-major, B col-major)
__device__ __forceinline__ void mma16816(float* d, const u32* a, u32 b0, u32 b1) {
    asm volatile("mma.sync.aligned.m16n8k16.row.col.f32.bf16.bf16.f32 "
        "{%0,%1,%2,%3}, {%4,%5,%6,%7}, {%8,%9}, {%0,%1,%2,%3};"
        : "+f"(d[0]), "+f"(d[1]), "+f"(d[2]), "+f"(d[3])
        : "r"(a[0]), "r"(a[1]), "r"(a[2]), "r"(a[3]), "r"(b0), "r"(b1));
}
__device__ __forceinline__ void ldsm4(u32* r, u32 addr) {
    asm volatile("ldmatrix.sync.aligned.m8n8.x4.shared.b16 {%0,%1,%2,%3}, [%4];"
        : "=r"(r[0]), "=r"(r[1]), "=r"(r[2]), "=r"(r[3]) : "r"(addr));
}

// ---------------------------------------------------------------------------
// Weight prep: W^T split hi/lo, [w][n][WPAD] bf16. w: 0=q,1=k,2=v,3=g,4=o
// ---------------------------------------------------------------------------
__global__ void prep_w_kernel(const float* __restrict__ wq, const float* __restrict__ wk,
                              const float* __restrict__ wv, const float* __restrict__ wg,
                              const float* __restrict__ wo) {
    int w = blockIdx.x;
    const float* W = (w == 0) ? wq : (w == 1) ? wk : (w == 2) ? wv : (w == 3) ? wg : wo;
    u32* oh = (u32*)g_wh + (size_t)w*C*(WPAD/2);
    u32* ol = (u32*)g_wl + (size_t)w*C*(WPAD/2);
    for (int i = threadIdx.x; i < C*64; i += blockDim.x) {
        int n = i >> 6, kp = i & 63;
        float f0 = W[(2*kp)*C + n], f1 = W[(2*kp+1)*C + n];
        u32 h = pack_bf2(f0, f1);
        oh[n*(WPAD/2) + kp] = h;
        ol[n*(WPAD/2) + kp] = pack_bf2(f0 - lo_f(h), f1 - hi_f(h));
    }
}

// ---------------------------------------------------------------------------
// LayerNorm + per-head pair bias; x written as SPLIT bf16.
// ---------------------------------------------------------------------------
__global__ void ln_bias_kernel(const float* __restrict__ pair,
                               const float* __restrict__ ln_w,
                               const float* __restrict__ ln_b,
                               const float* __restrict__ w_bias) {
    int warp = threadIdx.x >> 5, lane = threadIdx.x & 31;
    int row0 = (blockIdx.x * 8 + warp) * 2;
    float4 lw = ((const float4*)ln_w)[lane];
    float4 lb = ((const float4*)ln_b)[lane];
    float4 wb0 = ((const float4*)w_bias)[lane*4 + 0];
    float4 wb1 = ((const float4*)w_bias)[lane*4 + 1];
    float4 wb2 = ((const float4*)w_bias)[lane*4 + 2];
    float4 wb3 = ((const float4*)w_bias)[lane*4 + 3];
    #pragma unroll
    for (int rr = 0; rr < 2; rr++) {
        int row = row0 + rr;
        float4 x = ((const float4*)(pair + (size_t)row * C))[lane];
        float s = x.x + x.y + x.z + x.w;
        #pragma unroll
        for (int o = 16; o; o >>= 1) s += __shfl_xor_sync(0xffffffffu, s, o);
        float mu = s * (1.0f / C);
        float dx = x.x-mu, dy = x.y-mu, dz = x.z-mu, dw = x.w-mu;
        float s2 = dx*dx + dy*dy + dz*dz + dw*dw;
        #pragma unroll
        for (int o = 16; o; o >>= 1) s2 += __shfl_xor_sync(0xffffffffu, s2, o);
        float rstd = rsqrtf(s2 * (1.0f / C) + 1e-5f);
        float4 y;
        y.x = dx*rstd*lw.x + lb.x;  y.y = dy*rstd*lw.y + lb.y;
        y.z = dz*rstd*lw.z + lb.z;  y.w = dw*rstd*lw.w + lb.w;
        u32 h0 = pack_bf2(y.x, y.y), h1 = pack_bf2(y.z, y.w);
        u32 l0 = pack_bf2(y.x - lo_f(h0), y.y - hi_f(h0));
        u32 l1 = pack_bf2(y.z - lo_f(h1), y.w - hi_f(h1));
        ((u32*)g_xh)[(size_t)row*64 + lane*2]     = h0;
        ((u32*)g_xh)[(size_t)row*64 + lane*2 + 1] = h1;
        ((u32*)g_xl)[(size_t)row*64 + lane*2]     = l0;
        ((u32*)g_xl)[(size_t)row*64 + lane*2 + 1] = l1;
        float4 bs;
        bs.x = y.x*wb0.x + y.y*wb1.x + y.z*wb2.x + y.w*wb3.x;
        bs.y = y.x*wb0.y + y.y*wb1.y + y.z*wb2.y + y.w*wb3.y;
        bs.z = y.x*wb0.z + y.y*wb1.z + y.z*wb2.z + y.w*wb3.z;
        bs.w = y.x*wb0.w + y.y*wb1.w + y.z*wb2.w + y.w*wb3.w;
        #pragma unroll
        for (int o = 16; o; o >>= 1) {
            bs.x += __shfl_xor_sync(0xffffffffu, bs.x, o);
            bs.y += __shfl_xor_sync(0xffffffffu, bs.y, o);
            bs.z += __shfl_xor_sync(0xffffffffu, bs.z, o);
            bs.w += __shfl_xor_sync(0xffffffffu, bs.w, o);
        }
        if (lane == 0) {
            g_bias[0*NN + row] = bs.x;  g_bias[1*NN + row] = bs.y;
            g_bias[2*NN + row] = bs.z;  g_bias[3*NN + row] = bs.w;
        }
    }
}

// ---------------------------------------------------------------------------
// Shared MMA-GEMM core: A-split + W-split in smem, warp tile 32x64.
// smem u32 layout: Ah[128*68] | Al | Wh | Wl
// ---------------------------------------------------------------------------
#define SM_A_H 0
#define SM_A_L (128*68)
#define SM_W_H (2*128*68)
#define SM_W_L (3*128*68)
#define GEMM_SMEM_BYTES (4*128*68*4)

__device__ __forceinline__ void stage_w(u32* smu, int w, int tid) {
    const u32* wh = (const u32*)g_wh + (size_t)w*C*(WPAD/2);
    const u32* wl = (const u32*)g_wl + (size_t)w*C*(WPAD/2);
    for (int i = tid; i < 128*64; i += 256) {
        int n = i >> 6, kp = i & 63;
        smu[SM_W_H + n*68 + kp] = wh[n*68 + kp];
        smu[SM_W_L + n*68 + kp] = wl[n*68 + kp];
    }
}

// compute one (weight-resident) 128x128 GEMM into acc via ldmatrix + 3-combo MMA
__device__ __forceinline__ void gemm_core(u32 sb, int wm, int wn, int lane, int mt,
                                          float acc[8][4]) {
    int r = lane & 7, sel = lane >> 3;
    u32 aBaseH = sb + (SM_A_H*4) + ((wm*32 + (sel&1)*8 + r)*WPAD + (sel>>1)*8)*2
               + mt*16*WPAD*2;
    u32 aBaseL = aBaseH + (SM_A_L - SM_A_H)*4;
    u32 bBaseH = sb + (SM_W_H*4) + ((wn*64 + (sel>>1)*8 + r)*WPAD + (sel&1)*8)*2;
    u32 bBaseL = bBaseH + (SM_W_L - SM_W_H)*4;
    #pragma unroll
    for (int ks = 0; ks < 8; ks++) {
        u32 ah[4], al[4];
        ldsm4(ah, aBaseH + ks*32);
        ldsm4(al, aBaseL + ks*32);
        #pragma unroll
        for (int p = 0; p < 4; p++) {
            u32 bh[4], bl[4];
            ldsm4(bh, bBaseH + (p*16*WPAD + ks*16)*2);
            ldsm4(bl, bBaseL + (p*16*WPAD + ks*16)*2);
            mma16816(acc[2*p],   ah, bh[0], bh[1]);
            mma16816(acc[2*p],   ah, bl[0], bl[1]);
            mma16816(acc[2*p],   al, bh[0], bh[1]);
            mma16816(acc[2*p+1], ah, bh[2], bh[3]);
            mma16816(acc[2*p+1], ah, bl[2], bl[3]);
            mma16816(acc[2*p+1], al, bh[2], bh[3]);
        }
    }
}

// ---------------------------------------------------------------------------
// QKVG projections via mma.sync. Q/K/V epilogue: split bf16; gate: sigmoid fp32.
// ---------------------------------------------------------------------------
__global__ __launch_bounds__(256) void proj_mma_kernel() {
    extern __shared__ u32 smu[];
    u32 sb = smem_u32(smu);
    int tid = threadIdx.x, wid = tid >> 5, lane = tid & 31;
    int wm = wid & 3, wn = wid >> 2;
    int g = lane >> 2, t = lane & 3;
    int rowBase = blockIdx.x * 128;

    const u32* xh = (const u32*)g_xh + (size_t)rowBase*64;
    const u32* xl = (const u32*)g_xl + (size_t)rowBase*64;
    for (int i = tid; i < 128*64; i += 256) {
        int row = i >> 6, c = i & 63;
        smu[SM_A_H + row*68 + c] = xh[row*64 + c];
        smu[SM_A_L + row*68 + c] = xl[row*64 + c];
    }

    for (int w = 0; w < 4; w++) {
        stage_w(smu, w, tid);
        __syncthreads();
        #pragma unroll
        for (int mt = 0; mt < 2; mt++) {
            float acc[8][4];
            #pragma unroll
            for (int nt = 0; nt < 8; nt++)
                #pragma unroll
                for (int j = 0; j < 4; j++) acc[nt][j] = 0.f;
            gemm_core(sb, wm, wn, lane, mt, acc);

            size_t row0 = (size_t)rowBase + wm*32 + mt*16 + g;
            size_t row1 = row0 + 8;
            if (w < 3) {
                u32* Oh = (u32*)((w == 0) ? g_qh : (w == 1) ? g_kh : g_vh);
                u32* Ol = (u32*)((w == 0) ? g_ql : (w == 1) ? g_kl : g_vl);
                #pragma unroll
                for (int nt = 0; nt < 8; nt++) {
                    int cp = wn*32 + nt*4 + t;
                    u32 h0 = pack_bf2(acc[nt][0], acc[nt][1]);
                    u32 h1 = pack_bf2(acc[nt][2], acc[nt][3]);
                    Oh[row0*64 + cp] = h0;
                    Ol[row0*64 + cp] = pack_bf2(acc[nt][0] - lo_f(h0), acc[nt][1] - hi_f(h0));
                    Oh[row1*64 + cp] = h1;
                    Ol[row1*64 + cp] = pack_bf2(acc[nt][2] - lo_f(h1), acc[nt][3] - hi_f(h1));
                }
            } else {
                #pragma unroll
                for (int nt = 0; nt < 8; nt++) {
                    int col = wn*64 + nt*8 + 2*t;
                    float2 v0, v1;
                    v0.x = 1.f/(1.f + __expf(-acc[nt][0]));
                    v0.y = 1.f/(1.f + __expf(-acc[nt][1]));
                    v1.x = 1.f/(1.f + __expf(-acc[nt][2]));
                    v1.y = 1.f/(1.f + __expf(-acc[nt][3]));
                    *(float2*)&g_g[row0*C + col] = v0;
                    *(float2*)&g_g[row1*C + col] = v1;
                }
            }
        }
        __syncthreads();
    }
}

// ---------------------------------------------------------------------------
// Output projection via mma.sync: (o * gate) @ wo -> fp32 d_out.
// ---------------------------------------------------------------------------
__global__ __launch_bounds__(256) void out_mma_kernel(float* __restrict__ Out) {
    extern __shared__ u32 smu[];
    u32 sb = smem_u32(smu);
    int tid = threadIdx.x, wid = tid >> 5, lane = tid & 31;
    int wm = wid & 3, wn = wid >> 2;
    int g = lane >> 2, t = lane & 3;
    int rowBase = blockIdx.x * 128;

    const float4* op = (const float4*)(g_o + (size_t)rowBase*C);
    const float4* gp = (const float4*)(g_g + (size_t)rowBase*C);
    for (int i = tid; i < 128*32; i += 256) {
        int row = i >> 5, c = i & 31;
        float4 a = op[row*32 + c], b = gp[row*32 + c];
        a.x *= b.x; a.y *= b.y; a.z *= b.z; a.w *= b.w;
        u32 h0 = pack_bf2(a.x, a.y), h1 = pack_bf2(a.z, a.w);
        smu[SM_A_H + row*68 + 2*c]     = h0;
        smu[SM_A_H + row*68 + 2*c + 1] = h1;
        smu[SM_A_L + row*68 + 2*c]     = pack_bf2(a.x - lo_f(h0), a.y - hi_f(h0));
        smu[SM_A_L + row*68 + 2*c + 1] = pack_bf2(a.z - lo_f(h1), a.w - hi_f(h1));
    }
    stage_w(smu, 4, tid);
    __syncthreads();

    #pragma unroll
    for (int mt = 0; mt < 2; mt++) {
        float acc[8][4];
        #pragma unroll
        for (int nt = 0; nt < 8; nt++)
            #pragma unroll
            for (int j = 0; j < 4; j++) acc[nt][j] = 0.f;
        gemm_core(sb, wm, wn, lane, mt, acc);
        size_t row0 = (size_t)rowBase + wm*32 + mt*16 + g;
        size_t row1 = row0 + 8;
        #pragma unroll
        for (int nt = 0; nt < 8; nt++) {
            int col = wn*64 + nt*8 + 2*t;
            *(float2*)&Out[row0*C + col] = make_float2(acc[nt][0], acc[nt][1]);
            *(float2*)&Out[row1*C + col] = make_float2(acc[nt][2], acc[nt][3]);
        }
    }
}

// ---------------------------------------------------------------------------
// Attention via mma.sync (unchanged from the 942us version).
// ---------------------------------------------------------------------------
#define SM_MADD 0
#define SM_KH   1536
#define SM_KL   (SM_KH + 30720)
#define SM_VTH  (SM_KL + 30720)
#define SM_VTL  (SM_VTH + 25088)
#define AT_SMEM (SM_VTL + 25088)

__global__ __launch_bounds__(384) void attn_mma_kernel(const int* __restrict__ mask) {
    extern __shared__ char smem[];
    float* madd = (float*)(smem + SM_MADD);
    u32* Khs = (u32*)(smem + SM_KH);              // row stride 20 u32
    u32* Kls = (u32*)(smem + SM_KL);
    uint16_t* Vth = (uint16_t*)(smem + SM_VTH);   // [32 d][392 keys]
    uint16_t* Vtl = (uint16_t*)(smem + SM_VTL);

    int b = blockIdx.x, h = blockIdx.y;
    int tid = threadIdx.x, warp = tid >> 5, lane = tid & 31;
    int g = lane >> 2, t = lane & 3;
    const float scale = 0.17677669529663687f;   // 1/sqrt(32)

    const u32* KH = (const u32*)g_kh;  const u32* KL = (const u32*)g_kl;
    const u32* VH = (const u32*)g_vh;  const u32* VL = (const u32*)g_vl;
    const u32* QH = (const u32*)g_qh;  const u32* QL = (const u32*)g_ql;

    for (int i = tid; i < N; i += 384)
        madd[i] = (mask[b*N + i] > 0 ? 0.f : -1e9f) - 4.0f;
    for (int i = tid; i < N*16; i += 384) {
        int key = i >> 4, dp = i & 15;
        size_t gi = (size_t)(b*N + key)*64 + h*16 + dp;
        Khs[key*20 + dp] = KH[gi];
        Kls[key*20 + dp] = KL[gi];
        u32 vh = VH[gi], vl = VL[gi];
        Vth[(2*dp)*392 + key]   = (uint16_t)(vh & 0xFFFFu);
        Vth[(2*dp+1)*392 + key] = (uint16_t)(vh >> 16);
        Vtl[(2*dp)*392 + key]   = (uint16_t)(vl & 0xFFFFu);
        Vtl[(2*dp+1)*392 + key] = (uint16_t)(vl >> 16);
    }
    __syncthreads();

    const u32* Vth32 = (const u32*)Vth;   // row stride 196 u32
    const u32* Vtl32 = (const u32*)Vtl;

    for (int mt = 0; mt < 2; mt++) {
        int qb = warp*32 + mt*16;
        u32 qh[2][4], ql[2][4];
        #pragma unroll
        for (int ks = 0; ks < 2; ks++) {
            size_t base0 = (size_t)(b*N + qb + g)*64 + h*16 + ks*8 + t;
            size_t base1 = base0 + 8*64;
            qh[ks][0] = QH[base0];     qh[ks][1] = QH[base1];
            qh[ks][2] = QH[base0 + 4]; qh[ks][3] = QH[base1 + 4];
            ql[ks][0] = QL[base0];     ql[ks][1] = QL[base1];
            ql[ks][2] = QL[base0 + 4]; ql[ks][3] = QL[base1 + 4];
        }
        float oacc[4][4];
        #pragma unroll
        for (int dt = 0; dt < 4; dt++)
            #pragma unroll
            for (int j = 0; j < 4; j++) oacc[dt][j] = 0.f;
        float sum0 = 0.f, sum1 = 0.f;
        const float* bias0 = g_bias + (size_t)h*NN + (size_t)(qb + g)*N;
        const float* bias1 = bias0 + 8*N;

        for (int kb = 0; kb < N; kb += 16) {
            float s0[4] = {0.f,0.f,0.f,0.f}, s1[4] = {0.f,0.f,0.f,0.f};
            #pragma unroll
            for (int ks = 0; ks < 2; ks++) {
                int k0 = (kb + g)*20 + ks*8 + t;
                int k1 = k0 + 8*20;
                u32 b0h = Khs[k0], b1h = Khs[k0+4];
                u32 b0l = Kls[k0], b1l = Kls[k0+4];
                mma16816(s0, qh[ks], b0h, b1h);
                mma16816(s0, qh[ks], b0l, b1l);
                mma16816(s0, ql[ks], b0h, b1h);
                u32 c0h = Khs[k1], c1h = Khs[k1+4];
                u32 c0l = Kls[k1], c1l = Kls[k1+4];
                mma16816(s1, qh[ks], c0h, c1h);
                mma16816(s1, qh[ks], c0l, c1l);
                mma16816(s1, ql[ks], c0h, c1h);
            }
            float2 bA0 = *(const float2*)&bias0[kb + 2*t];
            float2 bB0 = *(const float2*)&bias1[kb + 2*t];
            float2 bA1 = *(const float2*)&bias0[kb + 8 + 2*t];
            float2 bB1 = *(const float2*)&bias1[kb + 8 + 2*t];
            float2 mA0 = *(const float2*)&madd[kb + 2*t];
            float2 mA1 = *(const float2*)&madd[kb + 8 + 2*t];
            float e00 = __expf(fmaf(s0[0], scale, bA0.x + mA0.x));
            float e01 = __expf(fmaf(s0[1], scale, bA0.y + mA0.y));
            float e02 = __expf(fmaf(s0[2], scale, bB0.x + mA0.x));
            float e03 = __expf(fmaf(s0[3], scale, bB0.y + mA0.y));
            float e10 = __expf(fmaf(s1[0], scale, bA1.x + mA1.x));
            float e11 = __expf(fmaf(s1[1], scale, bA1.y + mA1.y));
            float e12 = __expf(fmaf(s1[2], scale, bB1.x + mA1.x));
            float e13 = __expf(fmaf(s1[3], scale, bB1.y + mA1.y));
            sum0 += (e00 + e01) + (e10 + e11);
            sum1 += (e02 + e03) + (e12 + e13);
            u32 ah[4], al[4];
            ah[0] = pack_bf2(e00, e01);  ah[1] = pack_bf2(e02, e03);
            ah[2] = pack_bf2(e10, e11);  ah[3] = pack_bf2(e12, e13);
            al[0] = pack_bf2(e00 - lo_f(ah[0]), e01 - hi_f(ah[0]));
            al[1] = pack_bf2(e02 - lo_f(ah[1]), e03 - hi_f(ah[1]));
            al[2] = pack_bf2(e10 - lo_f(ah[2]), e11 - hi_f(ah[2]));
            al[3] = pack_bf2(e12 - lo_f(ah[3]), e13 - hi_f(ah[3]));
            int kcol = (kb >> 1) + t;
            #pragma unroll
            for (int dt = 0; dt < 4; dt++) {
                int vr = (dt*8 + g)*196;
                u32 v0h = Vth32[vr + kcol], v1h = Vth32[vr + kcol + 4];
                u32 v0l = Vtl32[vr + kcol], v1l = Vtl32[vr + kcol + 4];
                mma16816(oacc[dt], ah, v0h, v1h);
                mma16816(oacc[dt], ah, v0l, v1l);
                mma16816(oacc[dt], al, v0h, v1h);
            }
        }
        sum0 += __shfl_xor_sync(0xffffffffu, sum0, 1);
        sum0 += __shfl_xor_sync(0xffffffffu, sum0, 2);
        sum1 += __shfl_xor_sync(0xffffffffu, sum1, 1);
        sum1 += __shfl_xor_sync(0xffffffffu, sum1, 2);
        float inv0 = 1.f / sum0, inv1 = 1.f / sum1;
        float* o0 = g_o + (size_t)(b*N + qb + g)*C + h*DH;
        float* o1 = o0 + 8*C;
        #pragma unroll
        for (int dt = 0; dt < 4; dt++) {
            *(float2*)&o0[dt*8 + 2*t] = make_float2(oacc[dt][0]*inv0, oacc[dt][1]*inv0);
            *(float2*)&o1[dt*8 + 2*t] = make_float2(oacc[dt][2]*inv1, oacc[dt][3]*inv1);
        }
    }
}

// ---------------------------------------------------------------------------
extern "C" void kernel_launch(void* const* d_in, const int* in_sizes, int n_in,
                              void* d_out, int out_size) {
    const float* pair   = (const float*)d_in[0];
    const int*   mask   = (const int*)  d_in[1];
    const float* ln_w   = (const float*)d_in[2];
    const float* ln_b   = (const float*)d_in[3];
    const float* w_bias = (const float*)d_in[4];
    const float* wq     = (const float*)d_in[5];
    const float* wk     = (const float*)d_in[6];
    const float* wv     = (const float*)d_in[7];
    const float* wg     = (const float*)d_in[8];
    const float* wo     = (const float*)d_in[9];

    cudaFuncSetAttribute(proj_mma_kernel, cudaFuncAttributeMaxDynamicSharedMemorySize,
                         GEMM_SMEM_BYTES);
    cudaFuncSetAttribute(out_mma_kernel, cudaFuncAttributeMaxDynamicSharedMemorySize,
                         GEMM_SMEM_BYTES);
    cudaFuncSetAttribute(attn_mma_kernel, cudaFuncAttributeMaxDynamicSharedMemorySize,
                         AT_SMEM);

    prep_w_kernel<<<5, 256>>>(wq, wk, wv, wg, wo);
    ln_bias_kernel<<<NN/16, 256>>>(pair, ln_w, ln_b, w_bias);
    proj_mma_kernel<<<NN/128, 256, GEMM_SMEM_BYTES>>>();
    attn_mma_kernel<<<dim3(N, H), 384, AT_SMEM>>>(mask);
    out_mma_kernel<<<NN/128, 256, GEMM_SMEM_BYTES>>>((float*)d_out);
}